// round 15
// baseline (speedup 1.0000x reference)
#include <cuda_runtime.h>
#include <cstdint>
#include <cstddef>

#define BATCH 8
#define P 2048
#define D 64
#define FEPS 0.1f
// log2(e)/eps
#define INV 14.426950408889634f
// eps*ln(2)
#define EPSLN2 0.06931471805599453f
#define NMAT ((size_t)BATCH * P * P)
#define GATE 30.0f

// ---------------- scratch (static device globals; no runtime allocation) ----
__device__ __align__(16) float g_u[BATCH * P];
__device__ __align__(16) float g_v[BATCH * P];
__device__ float g_xn[BATCH * P];
__device__ float g_yn[BATCH * P];
__device__ float g_errp[BATCH * P];      // per-row |du|
__device__ float g_costp[BATCH * P];     // per-row pi*C partials
__device__ int   g_done[2];              // parity double-buffered freeze flag
__device__ __align__(16) float4 g_ct4[NMAT / 4];  // C transposed (134MB scratch)

__device__ __forceinline__ float ex2f(float x) {
    float r; asm("ex2.approx.f32 %0, %1;" : "=f"(r) : "f"(x)); return r;
}
__device__ __forceinline__ float lg2f_(float x) {
    float r; asm("lg2.approx.f32 %0, %1;" : "=f"(r) : "f"(x)); return r;
}
__device__ __forceinline__ float eps_log_marginal() {
    return FEPS * logf(1.0f / 2048.0f + 1e-8f);
}

// ---------------- init --------------------------------------------------------
__global__ void k_init() {
    int i = blockIdx.x * blockDim.x + threadIdx.x;
    if (i < BATCH * P) { g_u[i] = 0.0f; g_v[i] = 0.0f; }
    if (i == 0) { g_done[0] = 0; g_done[1] = 0; }
}

// ---------------- squared norms (warp per point) ------------------------------
__global__ void k_norm(const float* __restrict__ x, const float* __restrict__ y) {
    int gw   = (blockIdx.x * blockDim.x + threadIdx.x) >> 5;
    int lane = threadIdx.x & 31;
    if (gw >= 2 * BATCH * P) return;
    bool isx = gw < BATCH * P;
    int p = isx ? gw : gw - BATCH * P;
    const float* src = isx ? x : y;
    float a0 = src[(size_t)p * D + lane];
    float a1 = src[(size_t)p * D + 32 + lane];
    float s = a0 * a0 + a1 * a1;
    #pragma unroll
    for (int o = 16; o; o >>= 1) s += __shfl_xor_sync(0xffffffffu, s, o);
    if (lane == 0) (isx ? g_xn : g_yn)[p] = s;
}

// ---------------- C = ||x||^2 + ||y||^2 - 2 x.y  (+ transposed copy) ----------
__global__ void k_costmat(const float* __restrict__ x, const float* __restrict__ y,
                          float* __restrict__ Cout) {
    __shared__ float xs[64][65];
    __shared__ float ys[64][65];
    int b  = blockIdx.z;
    int i0 = blockIdx.y * 64;
    int j0 = blockIdx.x * 64;
    int tid = threadIdx.x;

    const float* xb = x + ((size_t)b * P + i0) * D;
    const float* yb = y + ((size_t)b * P + j0) * D;
    #pragma unroll
    for (int idx = tid; idx < 4096; idx += 256) {
        int p = idx >> 6, d = idx & 63;
        xs[d][p] = xb[(size_t)p * D + d];
        ys[d][p] = yb[(size_t)p * D + d];
    }
    __syncthreads();

    int tx = tid & 15, ty = tid >> 4;
    float acc[4][4];
    #pragma unroll
    for (int r = 0; r < 4; r++)
        #pragma unroll
        for (int c = 0; c < 4; c++) acc[r][c] = 0.0f;

    #pragma unroll 8
    for (int k = 0; k < 64; k++) {
        float rx[4], ry[4];
        #pragma unroll
        for (int r = 0; r < 4; r++) rx[r] = xs[k][ty * 4 + r];
        #pragma unroll
        for (int c = 0; c < 4; c++) ry[c] = ys[k][tx * 4 + c];
        #pragma unroll
        for (int r = 0; r < 4; r++)
            #pragma unroll
            for (int c = 0; c < 4; c++) acc[r][c] = fmaf(rx[r], ry[c], acc[r][c]);
    }

    float xnr[4], ynr[4];
    #pragma unroll
    for (int r = 0; r < 4; r++) xnr[r] = g_xn[b * P + i0 + ty * 4 + r];
    #pragma unroll
    for (int c = 0; c < 4; c++) ynr[c] = g_yn[b * P + j0 + tx * 4 + c];

    float val[4][4];
    #pragma unroll
    for (int r = 0; r < 4; r++)
        #pragma unroll
        for (int c = 0; c < 4; c++)
            val[r][c] = xnr[r] + ynr[c] - 2.0f * acc[r][c];

    #pragma unroll
    for (int r = 0; r < 4; r++) {
        int row = i0 + ty * 4 + r;
        float4 v4 = make_float4(val[r][0], val[r][1], val[r][2], val[r][3]);
        *reinterpret_cast<float4*>(Cout + ((size_t)b * P + row) * P + j0 + tx * 4) = v4;
    }

    __syncthreads();
    #pragma unroll
    for (int r = 0; r < 4; r++)
        #pragma unroll
        for (int c = 0; c < 4; c++)
            xs[ty * 4 + r][tx * 4 + c] = val[r][c];
    __syncthreads();
    float* CT = (float*)g_ct4;
    #pragma unroll
    for (int idx = tid; idx < 4096; idx += 256) {
        int jj = idx >> 6, ii = idx & 63;
        CT[((size_t)b * P + (j0 + jj)) * P + (i0 + ii)] = xs[ii][jj];
    }
}

// ---------------- high-occupancy streaming row-LSE pass -----------------------
// One 256-thread block per 4-row tile (grid 4096, non-persistent). 2 warps per
// row; 8 batched LDG.128 per thread (MLP 8); per-group maxima qm[8] keep regs
// low so ~6 blocks (48 warps) are resident per SM. Pass 2 re-reads only
// candidate q-groups (L1/L2-hot) and issues EX2 only there.
template<bool UPASS>
__global__ void __launch_bounds__(256, 6) k_row(const float4* __restrict__ Cg4, int par) {
    if (g_done[par]) {
        if (!UPASS && blockIdx.x == 0 && threadIdx.x == 0) g_done[par ^ 1] = 1;
        return;
    }
    const float4* M4   = UPASS ? Cg4 : (const float4*)g_ct4;
    const float*  wv   = UPASS ? g_v : g_u;
    float*        outv = UPASS ? g_u : g_v;

    __shared__ __align__(16) float vw[P];
    __shared__ float sm[8];
    __shared__ float ss[8];
    __shared__ float red[256];

    int tid = threadIdx.x, lane = tid & 31, warp = tid >> 5;
    int row4 = warp >> 1;          // 0..3 : row within this block's tile
    int half = warp & 1;           // 0/1  : which half of the row
    int b = blockIdx.x >> 9;       // 512 blocks per batch

    // v-pass block 0: fold convergence check (g_errp complete from u-kernel)
    if (!UPASS && blockIdx.x == 0) {
        float e = 0.0f;
        for (int t = tid; t < BATCH * P; t += 256) e += g_errp[t];
        red[tid] = e;
        __syncthreads();
        for (int o = 128; o; o >>= 1) {
            if (tid < o) red[tid] += red[tid + o];
            __syncthreads();
        }
        if (tid == 0)
            g_done[par ^ 1] = (red[0] * (1.0f / BATCH) < 0.1f) ? 1 : 0;
    }

    // stage dual vector * INV into smem (8KB, coalesced, L2-hot source)
    {
        const float4* vb4 = reinterpret_cast<const float4*>(wv + b * P);
        float4* vs4 = reinterpret_cast<float4*>(vw);
        #pragma unroll
        for (int j = tid; j < 512; j += 256) {
            float4 t = __ldg(&vb4[j]);
            vs4[j] = make_float4(t.x * INV, t.y * INV, t.z * INV, t.w * INV);
        }
    }
    __syncthreads();

    int row = blockIdx.x * 4 + row4;
    const float4* R   = M4 + (size_t)row * 512 + half * 256;
    const float4* vv4 = reinterpret_cast<const float4*>(vw) + half * 256;

    // pass 1: per-group maxima of w = v*INV - C*INV (8 batched LDG.128)
    float qm[8];
    #pragma unroll
    for (int q = 0; q < 8; q++) {
        float4 c = __ldg(&R[lane + 32 * q]);
        float4 t = vv4[lane + 32 * q];
        float w0 = fmaf(c.x, -INV, t.x);
        float w1 = fmaf(c.y, -INV, t.y);
        float w2 = fmaf(c.z, -INV, t.z);
        float w3 = fmaf(c.w, -INV, t.w);
        qm[q] = fmaxf(fmaxf(w0, w1), fmaxf(w2, w3));
    }
    float lm = qm[0];
    #pragma unroll
    for (int q = 1; q < 8; q++) lm = fmaxf(lm, qm[q]);
    float mh = lm;
    #pragma unroll
    for (int o = 16; o; o >>= 1) mh = fmaxf(mh, __shfl_xor_sync(0xffffffffu, mh, o));
    if (lane == 0) sm[warp] = mh;
    __syncthreads();
    float m = fmaxf(sm[warp], sm[warp ^ 1]);   // full-row max

    // pass 2: re-read + EX2 only in candidate q-groups (hot in L1/L2)
    float ls = 0.0f;
    if (lm > m - GATE) {
        #pragma unroll
        for (int q = 0; q < 8; q++) {
            if (qm[q] > m - GATE) {
                float4 c = __ldg(&R[lane + 32 * q]);
                float4 t = vv4[lane + 32 * q];
                ls += ex2f(fmaf(c.x, -INV, t.x) - m);
                ls += ex2f(fmaf(c.y, -INV, t.y) - m);
                ls += ex2f(fmaf(c.z, -INV, t.z) - m);
                ls += ex2f(fmaf(c.w, -INV, t.w) - m);
            }
        }
    }
    #pragma unroll
    for (int o = 16; o; o >>= 1) ls += __shfl_xor_sync(0xffffffffu, ls, o);
    if (lane == 0) ss[warp] = ls;
    __syncthreads();

    if (half == 0 && lane == 0) {
        float tot = ss[warp] + ss[warp | 1];
        float nv = eps_log_marginal() - EPSLN2 * (m + lg2f_(tot));
        if (UPASS) {
            float old = outv[row];
            outv[row] = nv;
            g_errp[row] = fabsf(nv - old);
        } else {
            outv[row] = nv;
        }
    }
}

// ---------------- pi = exp((u+v-C)/eps), partial cost -------------------------
__global__ void __launch_bounds__(256) k_pi(const float4* __restrict__ C4,
                                            float4* __restrict__ pi4) {
    __shared__ __align__(16) float uvw[2048];
    __shared__ float sacc[256];
    int r = blockIdx.x, b = r >> 11, tid = threadIdx.x;
    float ug = g_u[r] * INV;
    for (int j = tid; j < 2048; j += 256) uvw[j] = fmaf(g_v[b * P + j], INV, ug);
    __syncthreads();

    const float4* Crow = C4 + (size_t)r * 512;
    float4* prow = pi4 + (size_t)r * 512;
    const float4* uvw4 = reinterpret_cast<const float4*>(uvw);
    float acc = 0.0f;
    #pragma unroll 2
    for (int j4 = tid; j4 < 512; j4 += 256) {
        float4 c = Crow[j4];
        float4 t = uvw4[j4];
        float4 p;
        p.x = ex2f(fmaf(c.x, -INV, t.x));
        p.y = ex2f(fmaf(c.y, -INV, t.y));
        p.z = ex2f(fmaf(c.z, -INV, t.z));
        p.w = ex2f(fmaf(c.w, -INV, t.w));
        prow[j4] = p;
        acc = fmaf(p.x, c.x, fmaf(p.y, c.y, fmaf(p.z, c.z, fmaf(p.w, c.w, acc))));
    }
    sacc[tid] = acc;
    __syncthreads();
    for (int o = 128; o; o >>= 1) {
        if (tid < o) sacc[tid] += sacc[tid + o];
        __syncthreads();
    }
    if (tid == 0) g_costp[r] = sacc[0];
}

__global__ void k_costred(float* __restrict__ costOut) {
    __shared__ float sb[256];
    int b = blockIdx.x;
    float e = 0.0f;
    for (int t = threadIdx.x; t < P; t += 256) e += g_costp[b * P + t];
    sb[threadIdx.x] = e;
    __syncthreads();
    for (int o = 128; o; o >>= 1) {
        if (threadIdx.x < o) sb[threadIdx.x] += sb[threadIdx.x + o];
        __syncthreads();
    }
    if (threadIdx.x == 0) costOut[b] = sb[0];
}

// ---------------- launch ------------------------------------------------------
extern "C" void kernel_launch(void* const* d_in, const int* in_sizes, int n_in,
                              void* d_out, int out_size) {
    (void)in_sizes; (void)n_in; (void)out_size;
    const float* x = (const float*)d_in[0];
    const float* y = (const float*)d_in[1];
    float* out  = (float*)d_out;
    float* cost = out;                      // [8]
    float* pi   = out + 8;                  // [8,2048,2048]
    float* Cm   = out + 8 + NMAT;           // [8,2048,2048]

    k_init<<<64, 256>>>();
    k_norm<<<4096, 256>>>(x, y);
    dim3 cg(32, 32, 8);
    k_costmat<<<cg, 256>>>(x, y, Cm);

    for (int k = 0; k < 100; k++) {
        int par = k & 1;
        k_row<true ><<<4096, 256>>>((const float4*)Cm, par);  // u (rows of C)
        k_row<false><<<4096, 256>>>((const float4*)Cm, par);  // v (rows of C^T)
    }

    k_pi<<<16384, 256>>>((const float4*)Cm, (float4*)pi);
    k_costred<<<8, 256>>>(cost);
}

// round 16
// speedup vs baseline: 1.6817x; 1.6817x over previous
#include <cuda_runtime.h>
#include <cstdint>
#include <cstddef>

#define BATCH 8
#define P 2048
#define D 64
#define FEPS 0.1f
// log2(e)/eps
#define INV 14.426950408889634f
// eps*ln(2)
#define EPSLN2 0.06931471805599453f
#define NMAT ((size_t)BATCH * P * P)
#define NT4 4096             // 4-row tiles (streaming kernel)
#define NT8 2048             // 8-row tiles (cand/fix kernels)
#define NBLK 296             // streaming: 2 blocks per SM
#define TILE_BYTES 32768u    // 4 rows * 2048 * 4B
#define FIX_BYTES 65536u     // 8 rows * 2048 * 4B
#define NSTAGE 3
#define GATE 30.0f
#define MARGIN 60.0f
#define KCAND 64
#define NITER 100
#define WARMUP 16
#define REBUILD 8

// ---------------- scratch (static device globals; no runtime allocation) ----
__device__ __align__(16) float g_u[BATCH * P];
__device__ __align__(16) float g_v[BATCH * P];
__device__ __align__(16) float g_ub[BATCH * P];
__device__ __align__(16) float g_vb[BATCH * P];
__device__ float g_xn[BATCH * P];
__device__ float g_yn[BATCH * P];
__device__ float g_errp[BATCH * P];      // per-row |du|
__device__ float g_costp[BATCH * P];
__device__ int   g_done[2];
__device__ __align__(16) float4 g_ct4[NMAT / 4];               // C^T fp32
__device__ __align__(16) uint2 g_candU[(size_t)BATCH * P * KCAND]; // 8MB
__device__ __align__(16) uint2 g_candV[(size_t)BATCH * P * KCAND]; // 8MB
__device__ float g_cutU[BATCH * P];
__device__ float g_cutV[BATCH * P];
__device__ int   g_flagU[NT8];
__device__ int   g_flagV[NT8];
__device__ unsigned int g_DuD[BATCH];    // encoded max drift of u since snapshot
__device__ unsigned int g_DvD[BATCH];    // encoded max drift of v since snapshot

__device__ __forceinline__ float ex2f(float x) {
    float r; asm("ex2.approx.f32 %0, %1;" : "=f"(r) : "f"(x)); return r;
}
__device__ __forceinline__ float lg2f_(float x) {
    float r; asm("lg2.approx.f32 %0, %1;" : "=f"(r) : "f"(x)); return r;
}
__device__ __forceinline__ float eps_log_marginal() {
    return FEPS * logf(1.0f / 2048.0f + 1e-8f);
}
__device__ __forceinline__ uint32_t smem_u32(const void* p) {
    return (uint32_t)__cvta_generic_to_shared(p);
}
__device__ __forceinline__ void mbar_wait(uint32_t mbar, uint32_t phase) {
    asm volatile(
        "{\n\t.reg .pred P;\n\t"
        "W%=: mbarrier.try_wait.parity.acquire.cta.shared::cta.b64 P, [%0], %1;\n\t"
        "@!P bra W%=;\n\t}"
        :: "r"(mbar), "r"(phase) : "memory");
}
__device__ __forceinline__ void issue_copy(uint32_t smem_dst, const void* src,
                                           uint32_t mbar, uint32_t bytes) {
    asm volatile("mbarrier.arrive.expect_tx.shared.b64 _, [%0], %1;"
                 :: "r"(mbar), "r"(bytes) : "memory");
    asm volatile("cp.async.bulk.shared::cta.global.mbarrier::complete_tx::bytes "
                 "[%0], [%1], %2, [%3];"
                 :: "r"(smem_dst), "l"(src), "r"(bytes), "r"(mbar) : "memory");
}
__device__ __forceinline__ unsigned int fenc(float f) {
    unsigned int u = __float_as_uint(f);
    return (u & 0x80000000u) ? ~u : (u | 0x80000000u);
}
__device__ __forceinline__ float fdec(unsigned int u) {
    unsigned int v = (u & 0x80000000u) ? (u & 0x7fffffffu) : ~u;
    return __uint_as_float(v);
}

// ---------------- init --------------------------------------------------------
__global__ void k_init() {
    int i = blockIdx.x * blockDim.x + threadIdx.x;
    if (i < BATCH * P) { g_u[i] = 0.0f; g_v[i] = 0.0f; }
    if (i == 0) { g_done[0] = 0; g_done[1] = 0; }
}

// ---------------- squared norms (warp per point) ------------------------------
__global__ void k_norm(const float* __restrict__ x, const float* __restrict__ y) {
    int gw   = (blockIdx.x * blockDim.x + threadIdx.x) >> 5;
    int lane = threadIdx.x & 31;
    if (gw >= 2 * BATCH * P) return;
    bool isx = gw < BATCH * P;
    int p = isx ? gw : gw - BATCH * P;
    const float* src = isx ? x : y;
    float a0 = src[(size_t)p * D + lane];
    float a1 = src[(size_t)p * D + 32 + lane];
    float s = a0 * a0 + a1 * a1;
    #pragma unroll
    for (int o = 16; o; o >>= 1) s += __shfl_xor_sync(0xffffffffu, s, o);
    if (lane == 0) (isx ? g_xn : g_yn)[p] = s;
}

// ---------------- C = ||x||^2 + ||y||^2 - 2 x.y  (+ transposed copy) ----------
__global__ void k_costmat(const float* __restrict__ x, const float* __restrict__ y,
                          float* __restrict__ Cout) {
    __shared__ float xs[64][65];
    __shared__ float ys[64][65];
    int b  = blockIdx.z;
    int i0 = blockIdx.y * 64;
    int j0 = blockIdx.x * 64;
    int tid = threadIdx.x;

    const float* xb = x + ((size_t)b * P + i0) * D;
    const float* yb = y + ((size_t)b * P + j0) * D;
    #pragma unroll
    for (int idx = tid; idx < 4096; idx += 256) {
        int p = idx >> 6, d = idx & 63;
        xs[d][p] = xb[(size_t)p * D + d];
        ys[d][p] = yb[(size_t)p * D + d];
    }
    __syncthreads();

    int tx = tid & 15, ty = tid >> 4;
    float acc[4][4];
    #pragma unroll
    for (int r = 0; r < 4; r++)
        #pragma unroll
        for (int c = 0; c < 4; c++) acc[r][c] = 0.0f;

    #pragma unroll 8
    for (int k = 0; k < 64; k++) {
        float rx[4], ry[4];
        #pragma unroll
        for (int r = 0; r < 4; r++) rx[r] = xs[k][ty * 4 + r];
        #pragma unroll
        for (int c = 0; c < 4; c++) ry[c] = ys[k][tx * 4 + c];
        #pragma unroll
        for (int r = 0; r < 4; r++)
            #pragma unroll
            for (int c = 0; c < 4; c++) acc[r][c] = fmaf(rx[r], ry[c], acc[r][c]);
    }

    float xnr[4], ynr[4];
    #pragma unroll
    for (int r = 0; r < 4; r++) xnr[r] = g_xn[b * P + i0 + ty * 4 + r];
    #pragma unroll
    for (int c = 0; c < 4; c++) ynr[c] = g_yn[b * P + j0 + tx * 4 + c];

    float val[4][4];
    #pragma unroll
    for (int r = 0; r < 4; r++)
        #pragma unroll
        for (int c = 0; c < 4; c++)
            val[r][c] = xnr[r] + ynr[c] - 2.0f * acc[r][c];

    #pragma unroll
    for (int r = 0; r < 4; r++) {
        int row = i0 + ty * 4 + r;
        float4 v4 = make_float4(val[r][0], val[r][1], val[r][2], val[r][3]);
        *reinterpret_cast<float4*>(Cout + ((size_t)b * P + row) * P + j0 + tx * 4) = v4;
    }

    __syncthreads();
    #pragma unroll
    for (int r = 0; r < 4; r++)
        #pragma unroll
        for (int c = 0; c < 4; c++)
            xs[ty * 4 + r][tx * 4 + c] = val[r][c];
    __syncthreads();
    float* CT = (float*)g_ct4;
    #pragma unroll
    for (int idx = tid; idx < 4096; idx += 256) {
        int jj = idx >> 6, ii = idx & 63;
        CT[((size_t)b * P + (j0 + jj)) * P + (i0 + ii)] = xs[ii][jj];
    }
}

// ---------------- streaming row-LSE pass (R14, proven 33.7us) ----------------
template<bool UPASS>
__global__ void __launch_bounds__(256, 2) k_lse_pipe(const float* __restrict__ Cg, int par) {
    if (g_done[par]) {
        if (!UPASS && blockIdx.x == 0 && threadIdx.x == 0) g_done[par ^ 1] = 1;
        return;
    }
    const float* M    = UPASS ? Cg : (const float*)g_ct4;
    const float* wv   = UPASS ? g_v : g_u;
    float*       outv = UPASS ? g_u : g_v;

    extern __shared__ __align__(128) float tile[];
    __shared__ float sm[8];
    __shared__ float ss[8];
    __shared__ float red[256];
    __shared__ __align__(8) unsigned long long mbars[NSTAGE];

    int tid = threadIdx.x, lane = tid & 31, warp = tid >> 5;
    int row4 = warp >> 1;
    int half = warp & 1;
    int t0 = (int)(((long long)blockIdx.x * NT4) / NBLK);
    int t1 = (int)(((long long)(blockIdx.x + 1) * NT4) / NBLK);

    uint32_t mb0 = smem_u32(&mbars[0]);
    if (tid == 0) {
        #pragma unroll
        for (int s = 0; s < NSTAGE; s++)
            asm volatile("mbarrier.init.shared.b64 [%0], 1;" :: "r"(mb0 + 8 * s) : "memory");
    }
    __syncthreads();
    if (tid == 0) {
        #pragma unroll
        for (int s = 0; s < NSTAGE; s++)
            if (t0 + s < t1)
                issue_copy(smem_u32(tile) + s * TILE_BYTES,
                           M + (size_t)(t0 + s) * (4 * P), mb0 + 8 * s, TILE_BYTES);
    }

    if (!UPASS && blockIdx.x == 0) {
        float e = 0.0f;
        for (int t = tid; t < BATCH * P; t += 256) e += g_errp[t];
        red[tid] = e;
        __syncthreads();
        for (int o = 128; o; o >>= 1) {
            if (tid < o) red[tid] += red[tid + o];
            __syncthreads();
        }
        if (tid == 0)
            g_done[par ^ 1] = (red[0] * (1.0f / BATCH) < 0.1f) ? 1 : 0;
    }

    float4 tv[8];
    int cur_b = -1;
    int phase[NSTAGE];
    #pragma unroll
    for (int s = 0; s < NSTAGE; s++) phase[s] = 0;

    for (int k = t0; k < t1; k++) {
        int b = k >> 9;
        if (b != cur_b) {
            const float4* vb4 = reinterpret_cast<const float4*>(wv + b * P);
            #pragma unroll
            for (int q = 0; q < 8; q++) {
                float4 t = vb4[half * 256 + lane + 32 * q];
                tv[q] = make_float4(t.x * INV, t.y * INV, t.z * INV, t.w * INV);
            }
            cur_b = b;
        }

        int s = (k - t0) % NSTAGE;
        mbar_wait(mb0 + 8 * s, (uint32_t)phase[s]);
        phase[s] ^= 1;

        const float4* R = reinterpret_cast<const float4*>(tile + s * 8192)
                          + row4 * 512 + half * 256;

        float lm = -3.4e38f;
        #pragma unroll
        for (int q = 0; q < 8; q++) {
            float4 c = R[lane + q * 32];
            float4 t = tv[q];
            lm = fmaxf(lm, fmaf(c.x, -INV, t.x));
            lm = fmaxf(lm, fmaf(c.y, -INV, t.y));
            lm = fmaxf(lm, fmaf(c.z, -INV, t.z));
            lm = fmaxf(lm, fmaf(c.w, -INV, t.w));
        }
        float mh = lm;
        #pragma unroll
        for (int o = 16; o; o >>= 1) mh = fmaxf(mh, __shfl_xor_sync(0xffffffffu, mh, o));
        if (lane == 0) sm[warp] = mh;
        __syncthreads();
        float m = fmaxf(sm[warp], sm[warp ^ 1]);

        float ls = 0.0f;
        if (lm > m - GATE) {
            #pragma unroll
            for (int q = 0; q < 8; q++) {
                float4 c = R[lane + q * 32];
                float4 t = tv[q];
                ls += ex2f(fmaf(c.x, -INV, t.x) - m);
                ls += ex2f(fmaf(c.y, -INV, t.y) - m);
                ls += ex2f(fmaf(c.z, -INV, t.z) - m);
                ls += ex2f(fmaf(c.w, -INV, t.w) - m);
            }
        }
        #pragma unroll
        for (int o = 16; o; o >>= 1) ls += __shfl_xor_sync(0xffffffffu, ls, o);
        if (lane == 0) ss[warp] = ls;
        __syncthreads();

        if (half == 0 && lane == 0) {
            float tot = ss[warp] + ss[warp | 1];
            float nv = eps_log_marginal() - EPSLN2 * (m + lg2f_(tot));
            int r = k * 4 + row4;
            if (UPASS) {
                float old = outv[r];
                outv[r] = nv;
                g_errp[r] = fabsf(nv - old);
            } else {
                outv[r] = nv;
            }
        }
        if (tid == 0 && k + NSTAGE < t1)
            issue_copy(smem_u32(tile) + s * TILE_BYTES,
                       M + (size_t)(k + NSTAGE) * (4 * P), mb0 + 8 * s, TILE_BYTES);
    }
}

// ---------------- snapshot + drift reset --------------------------------------
__global__ void k_snap(int par) {
    if (g_done[par]) return;
    int i = blockIdx.x * blockDim.x + threadIdx.x;
    if (i < BATCH * P) { g_ub[i] = g_u[i]; g_vb[i] = g_v[i]; }
    if (i < BATCH) { g_DuD[i] = fenc(0.0f); g_DvD[i] = fenc(0.0f); }
}

// ---------------- candidate list build (full stream per direction) ------------
template<bool UPASS>
__global__ void __launch_bounds__(256) k_build(const float* __restrict__ Cg, int par) {
    if (g_done[par]) return;
    const float* M    = UPASS ? Cg : (const float*)g_ct4;
    const float* dual = UPASS ? g_v : g_u;
    uint2* cand = UPASS ? g_candU : g_candV;
    float* cutw = UPASS ? g_cutU : g_cutV;

    extern __shared__ __align__(128) float ftile[];
    __shared__ __align__(16) float vw[P];
    __shared__ int scnt[8];
    __shared__ __align__(8) unsigned long long mbar;

    int tid = threadIdx.x, lane = tid & 31, warp = tid >> 5;
    int r0 = blockIdx.x * 8, b = r0 >> 11;
    uint32_t mb = smem_u32(&mbar);
    if (tid == 0)
        asm volatile("mbarrier.init.shared.b64 [%0], 1;" :: "r"(mb) : "memory");
    if (tid < 8) scnt[tid] = 0;
    __syncthreads();
    if (tid == 0) issue_copy(smem_u32(ftile), M + (size_t)r0 * P, mb, FIX_BYTES);

    const float4* db4 = reinterpret_cast<const float4*>(dual + b * P);
    float4* vw4 = reinterpret_cast<float4*>(vw);
    for (int j = tid; j < 512; j += 256) {
        float4 t = db4[j];
        vw4[j] = make_float4(t.x * INV, t.y * INV, t.z * INV, t.w * INV);
    }
    __syncthreads();
    mbar_wait(mb, 0);

    const float4* R = reinterpret_cast<const float4*>(ftile) + warp * 512;
    const float4* vv4 = reinterpret_cast<const float4*>(vw);

    float lm = -3.4e38f;
    #pragma unroll
    for (int q = 0; q < 16; q++) {
        float4 c = R[lane + q * 32];
        float4 t = vv4[lane + q * 32];
        lm = fmaxf(lm, fmaf(c.x, -INV, t.x));
        lm = fmaxf(lm, fmaf(c.y, -INV, t.y));
        lm = fmaxf(lm, fmaf(c.z, -INV, t.z));
        lm = fmaxf(lm, fmaf(c.w, -INV, t.w));
    }
    float m = lm;
    #pragma unroll
    for (int o = 16; o; o >>= 1) m = fmaxf(m, __shfl_xor_sync(0xffffffffu, m, o));

    int row = r0 + warp;
    float thr = m - MARGIN;
    #pragma unroll
    for (int q = 0; q < 16; q++) {
        float4 c = R[lane + q * 32];
        float4 t = vv4[lane + q * 32];
        int jb = 4 * (lane + 32 * q);
        float w0 = fmaf(c.x, -INV, t.x);
        float w1 = fmaf(c.y, -INV, t.y);
        float w2 = fmaf(c.z, -INV, t.z);
        float w3 = fmaf(c.w, -INV, t.w);
        if (w0 > thr) { int p = atomicAdd(&scnt[warp], 1); if (p < KCAND) cand[(size_t)row * KCAND + p] = make_uint2(__float_as_uint(c.x), jb + 0); }
        if (w1 > thr) { int p = atomicAdd(&scnt[warp], 1); if (p < KCAND) cand[(size_t)row * KCAND + p] = make_uint2(__float_as_uint(c.y), jb + 1); }
        if (w2 > thr) { int p = atomicAdd(&scnt[warp], 1); if (p < KCAND) cand[(size_t)row * KCAND + p] = make_uint2(__float_as_uint(c.z), jb + 2); }
        if (w3 > thr) { int p = atomicAdd(&scnt[warp], 1); if (p < KCAND) cand[(size_t)row * KCAND + p] = make_uint2(__float_as_uint(c.w), jb + 3); }
    }
    __syncthreads();
    int tot = scnt[warp];
    for (int s2 = tot + lane; s2 < KCAND; s2 += 32)
        cand[(size_t)row * KCAND + s2] = make_uint2(__float_as_uint(3.0e38f), 0);
    if (lane == 0)
        cutw[row] = (tot <= KCAND) ? (m - MARGIN) : 3.0e38f;
}

// ---------------- candidate LSE fast path -------------------------------------
template<bool UPASS>
__global__ void __launch_bounds__(256) k_cand(int par) {
    if (g_done[par]) {
        if (!UPASS && blockIdx.x == 0 && threadIdx.x == 0) g_done[par ^ 1] = 1;
        return;
    }
    __shared__ __align__(16) float vs[P];
    __shared__ float snv[8], sdrift[8];
    __shared__ int sdirty[8];
    __shared__ float red[256];

    int tid = threadIdx.x, lane = tid & 31, warp = tid >> 5;
    int base = blockIdx.x * 32;          // 32 rows per block
    int b = blockIdx.x >> 6;             // 64 blocks per batch

    const uint2* cand = UPASS ? g_candU : g_candV;
    const float* cutw = UPASS ? g_cutU : g_cutV;
    const float* dual = UPASS ? g_v : g_u;
    const float* snap = UPASS ? g_ub : g_vb;
    float*       outv = UPASS ? g_u : g_v;
    float Din = fdec(UPASS ? g_DvD[b] : g_DuD[b]);

    if (!UPASS && blockIdx.x == 0) {
        float e = 0.0f;
        for (int t = tid; t < BATCH * P; t += 256) e += g_errp[t];
        red[tid] = e;
        __syncthreads();
        for (int o = 128; o; o >>= 1) {
            if (tid < o) red[tid] += red[tid + o];
            __syncthreads();
        }
        if (tid == 0)
            g_done[par ^ 1] = (red[0] * (1.0f / BATCH) < 0.1f) ? 1 : 0;
    }

    const float4* db4 = reinterpret_cast<const float4*>(dual + b * P);
    float4* vs4 = reinterpret_cast<float4*>(vs);
    for (int j = tid; j < 512; j += 256) {
        float4 t = db4[j];
        vs4[j] = make_float4(t.x * INV, t.y * INV, t.z * INV, t.w * INV);
    }
    __syncthreads();

    float bdm = -3.4e38f;
    #pragma unroll 1
    for (int r = 0; r < 4; r++) {
        int row = base + r * 8 + warp;
        uint2 e0 = cand[(size_t)row * KCAND + lane];
        uint2 e1 = cand[(size_t)row * KCAND + 32 + lane];
        float w0 = vs[e0.y] - __uint_as_float(e0.x) * INV;
        float w1 = vs[e1.y] - __uint_as_float(e1.x) * INV;
        float lm = fmaxf(w0, w1);
        float m = lm;
        #pragma unroll
        for (int o = 16; o; o >>= 1) m = fmaxf(m, __shfl_xor_sync(0xffffffffu, m, o));
        float ls = 0.0f;
        if (lm > m - GATE) ls = ex2f(w0 - m) + ex2f(w1 - m);
        #pragma unroll
        for (int o = 16; o; o >>= 1) ls += __shfl_xor_sync(0xffffffffu, ls, o);
        float nv = eps_log_marginal() - EPSLN2 * (m + lg2f_(ls));
        float old = outv[row];
        if (lane == 0) {
            snv[warp] = nv;
            sdirty[warp] = (cutw[row] + INV * Din > m - GATE) ? 1 : 0;
            sdrift[warp] = nv - snap[row];
        }
        __syncthreads();
        int td = sdirty[0] | sdirty[1] | sdirty[2] | sdirty[3]
               | sdirty[4] | sdirty[5] | sdirty[6] | sdirty[7];
        int tile = blockIdx.x * 4 + r;
        if (tid == 0) {
            (UPASS ? g_flagU : g_flagV)[tile] = td;
            float dm = sdrift[0];
            #pragma unroll
            for (int i2 = 1; i2 < 8; i2++) dm = fmaxf(dm, sdrift[i2]);
            bdm = fmaxf(bdm, dm);
        }
        if (lane == 0 && !td) {
            outv[row] = nv;
            if (UPASS) g_errp[row] = fabsf(nv - old);
        }
        __syncthreads();
    }
    if (tid == 0)
        atomicMax(UPASS ? &g_DuD[b] : &g_DvD[b], fenc(bdm));
}

// ---------------- exact fallback for dirty tiles ------------------------------
template<bool UPASS>
__global__ void __launch_bounds__(256) k_fix(const float* __restrict__ Cg, int par) {
    if (g_done[par]) return;
    int tile = blockIdx.x;
    if (!((UPASS ? g_flagU : g_flagV)[tile])) return;

    const float* M    = UPASS ? Cg : (const float*)g_ct4;
    const float* dual = UPASS ? g_v : g_u;
    const float* snap = UPASS ? g_ub : g_vb;
    float*       outv = UPASS ? g_u : g_v;

    extern __shared__ __align__(128) float ftile[];
    __shared__ __align__(16) float vw[P];
    __shared__ float sdrift[8];
    __shared__ __align__(8) unsigned long long mbar;

    int tid = threadIdx.x, lane = tid & 31, warp = tid >> 5;
    int r0 = tile * 8, b = r0 >> 11;

    uint32_t mb = smem_u32(&mbar);
    if (tid == 0)
        asm volatile("mbarrier.init.shared.b64 [%0], 1;" :: "r"(mb) : "memory");
    __syncthreads();
    if (tid == 0) issue_copy(smem_u32(ftile), M + (size_t)r0 * P, mb, FIX_BYTES);

    const float4* db4 = reinterpret_cast<const float4*>(dual + b * P);
    float4* vw4 = reinterpret_cast<float4*>(vw);
    for (int j = tid; j < 512; j += 256) {
        float4 t = db4[j];
        vw4[j] = make_float4(t.x * INV, t.y * INV, t.z * INV, t.w * INV);
    }
    __syncthreads();
    mbar_wait(mb, 0);

    const float4* R = reinterpret_cast<const float4*>(ftile) + warp * 512;
    const float4* vv4 = reinterpret_cast<const float4*>(vw);

    float lm = -3.4e38f;
    #pragma unroll
    for (int q = 0; q < 16; q++) {
        float4 c = R[lane + q * 32];
        float4 t = vv4[lane + q * 32];
        lm = fmaxf(lm, fmaf(c.x, -INV, t.x));
        lm = fmaxf(lm, fmaf(c.y, -INV, t.y));
        lm = fmaxf(lm, fmaf(c.z, -INV, t.z));
        lm = fmaxf(lm, fmaf(c.w, -INV, t.w));
    }
    float m = lm;
    #pragma unroll
    for (int o = 16; o; o >>= 1) m = fmaxf(m, __shfl_xor_sync(0xffffffffu, m, o));

    float ls = 0.0f;
    if (lm > m - GATE) {
        #pragma unroll
        for (int q = 0; q < 16; q++) {
            float4 c = R[lane + q * 32];
            float4 t = vv4[lane + q * 32];
            ls += ex2f(fmaf(c.x, -INV, t.x) - m);
            ls += ex2f(fmaf(c.y, -INV, t.y) - m);
            ls += ex2f(fmaf(c.z, -INV, t.z) - m);
            ls += ex2f(fmaf(c.w, -INV, t.w) - m);
        }
    }
    #pragma unroll
    for (int o = 16; o; o >>= 1) ls += __shfl_xor_sync(0xffffffffu, ls, o);

    float nv = eps_log_marginal() - EPSLN2 * (m + lg2f_(ls));
    int row = r0 + warp;
    if (lane == 0) {
        float old = outv[row];
        outv[row] = nv;
        if (UPASS) g_errp[row] = fabsf(nv - old);
        sdrift[warp] = nv - snap[row];
    }
    __syncthreads();
    if (tid == 0) {
        float dm = sdrift[0];
        #pragma unroll
        for (int i2 = 1; i2 < 8; i2++) dm = fmaxf(dm, sdrift[i2]);
        atomicMax(UPASS ? &g_DuD[b] : &g_DvD[b], fenc(dm));
    }
}

// ---------------- pi = exp((u+v-C)/eps), partial cost -------------------------
__global__ void __launch_bounds__(256) k_pi(const float4* __restrict__ C4,
                                            float4* __restrict__ pi4) {
    __shared__ __align__(16) float uvw[2048];
    __shared__ float sacc[256];
    int r = blockIdx.x, b = r >> 11, tid = threadIdx.x;
    float ug = g_u[r] * INV;
    for (int j = tid; j < 2048; j += 256) uvw[j] = fmaf(g_v[b * P + j], INV, ug);
    __syncthreads();

    const float4* Crow = C4 + (size_t)r * 512;
    float4* prow = pi4 + (size_t)r * 512;
    const float4* uvw4 = reinterpret_cast<const float4*>(uvw);
    float acc = 0.0f;
    #pragma unroll 2
    for (int j4 = tid; j4 < 512; j4 += 256) {
        float4 c = Crow[j4];
        float4 t = uvw4[j4];
        float4 p;
        p.x = ex2f(fmaf(c.x, -INV, t.x));
        p.y = ex2f(fmaf(c.y, -INV, t.y));
        p.z = ex2f(fmaf(c.z, -INV, t.z));
        p.w = ex2f(fmaf(c.w, -INV, t.w));
        prow[j4] = p;
        acc = fmaf(p.x, c.x, fmaf(p.y, c.y, fmaf(p.z, c.z, fmaf(p.w, c.w, acc))));
    }
    sacc[tid] = acc;
    __syncthreads();
    for (int o = 128; o; o >>= 1) {
        if (tid < o) sacc[tid] += sacc[tid + o];
        __syncthreads();
    }
    if (tid == 0) g_costp[r] = sacc[0];
}

__global__ void k_costred(float* __restrict__ costOut) {
    __shared__ float sb[256];
    int b = blockIdx.x;
    float e = 0.0f;
    for (int t = threadIdx.x; t < P; t += 256) e += g_costp[b * P + t];
    sb[threadIdx.x] = e;
    __syncthreads();
    for (int o = 128; o; o >>= 1) {
        if (threadIdx.x < o) sb[threadIdx.x] += sb[threadIdx.x + o];
        __syncthreads();
    }
    if (threadIdx.x == 0) costOut[b] = sb[0];
}

// ---------------- launch ------------------------------------------------------
extern "C" void kernel_launch(void* const* d_in, const int* in_sizes, int n_in,
                              void* d_out, int out_size) {
    (void)in_sizes; (void)n_in; (void)out_size;
    const float* x = (const float*)d_in[0];
    const float* y = (const float*)d_in[1];
    float* out  = (float*)d_out;
    float* cost = out;                      // [8]
    float* pi   = out + 8;                  // [8,2048,2048]
    float* Cm   = out + 8 + NMAT;           // [8,2048,2048]

    cudaFuncSetAttribute(k_lse_pipe<true>,
                         cudaFuncAttributeMaxDynamicSharedMemorySize, NSTAGE * (int)TILE_BYTES);
    cudaFuncSetAttribute(k_lse_pipe<false>,
                         cudaFuncAttributeMaxDynamicSharedMemorySize, NSTAGE * (int)TILE_BYTES);
    cudaFuncSetAttribute(k_build<true>,
                         cudaFuncAttributeMaxDynamicSharedMemorySize, (int)FIX_BYTES);
    cudaFuncSetAttribute(k_build<false>,
                         cudaFuncAttributeMaxDynamicSharedMemorySize, (int)FIX_BYTES);
    cudaFuncSetAttribute(k_fix<true>,
                         cudaFuncAttributeMaxDynamicSharedMemorySize, (int)FIX_BYTES);
    cudaFuncSetAttribute(k_fix<false>,
                         cudaFuncAttributeMaxDynamicSharedMemorySize, (int)FIX_BYTES);

    k_init<<<64, 256>>>();
    k_norm<<<4096, 256>>>(x, y);
    dim3 cg(32, 32, 8);
    k_costmat<<<cg, 256>>>(x, y, Cm);

    // warmup: proven streaming iterations
    for (int k = 0; k < WARMUP; k++) {
        int par = k & 1;
        k_lse_pipe<true ><<<NBLK, 256, NSTAGE * TILE_BYTES>>>(Cm, par);
        k_lse_pipe<false><<<NBLK, 256, NSTAGE * TILE_BYTES>>>(Cm, par);
    }

    // candidate mode with periodic rebuild
    for (int k = WARMUP; k < NITER; k++) {
        int par = k & 1;
        if (((k - WARMUP) % REBUILD) == 0) {
            k_snap<<<64, 256>>>(par);
            k_build<true ><<<NT8, 256, FIX_BYTES>>>(Cm, par);
            k_build<false><<<NT8, 256, FIX_BYTES>>>(Cm, par);
        }
        k_cand<true ><<<512, 256>>>(par);
        k_fix<true ><<<NT8, 256, FIX_BYTES>>>(Cm, par);
        k_cand<false><<<512, 256>>>(par);
        k_fix<false><<<NT8, 256, FIX_BYTES>>>(Cm, par);
    }

    k_pi<<<16384, 256>>>((const float4*)Cm, (float4*)pi);
    k_costred<<<8, 256>>>(cost);
}